// round 4
// baseline (speedup 1.0000x reference)
#include <cuda_runtime.h>
#include <cuda_fp16.h>
#include <math.h>

#define BB 128       // batch
#define T_ENC 2048
#define T_DEC 256
#define HID 256
#define KEY 128
#define VAL 128
#define H1S 512      // lstm1 hidden
#define VOCAB 1000
#define NBLK 296     // 2 CTAs/SM * 148 SMs, all resident (launch_bounds(256,2))
#define NTHR 256

// ---------------- device scratch (static, allocated at module load) ------
__device__ unsigned g_bar;
__device__ float g_emb[T_DEC*BB*HID];                 // (t,b,h)
__device__ float g_h2ctx[(size_t)T_DEC*BB*(KEY+VAL)]; // (t,b,[h2|ctx])
__device__ float g_h1[2][BB*H1S];
__device__ float g_c1[BB*H1S];
__device__ float g_h2[2][BB*KEY];
__device__ float g_c2[BB*KEY];
__device__ float g_ctx[BB*VAL];
__device__ __align__(16) __half g_kh[(size_t)T_ENC*BB*KEY];
__device__ __align__(16) __half g_vh[(size_t)T_ENC*BB*VAL];

// ---------------- global software barrier (monotonic counter) ------------
__device__ __forceinline__ void gbar(unsigned target) {
    __syncthreads();
    if (threadIdx.x == 0) {
        __threadfence();
        atomicAdd(&g_bar, 1u);
        while (*(volatile unsigned*)&g_bar < target) __nanosleep(64);
        __threadfence();
    }
    __syncthreads();
}

__global__ void reset_bar_kernel() { g_bar = 0u; }

__device__ __forceinline__ float sigf(float x) { return 1.f / (1.f + expf(-x)); }

__device__ __forceinline__ float4 h4tof4(uint2 u) {
    __half2 a = *(__half2*)&u.x;
    __half2 b = *(__half2*)&u.y;
    float2 fa = __half22float2(a), fb = __half22float2(b);
    return make_float4(fa.x, fa.y, fb.x, fb.y);
}

// =============================================================================
// Persistent decoder kernel: pre-stage (init/embed/fp16-convert) + 256 steps of
// {gemm1+cell1, gemm2+cell2, attention}, separated by global barriers.
// =============================================================================
__global__ __launch_bounds__(NTHR, 2) void decoder_kernel(
    const float* __restrict__ keys, const float* __restrict__ values,
    const int* __restrict__ lens, const int* __restrict__ text,
    const float* __restrict__ emb_table,
    const float* __restrict__ Wih1, const float* __restrict__ Whh1,
    const float* __restrict__ bih1, const float* __restrict__ bhh1,
    const float* __restrict__ Wih2, const float* __restrict__ Whh2,
    const float* __restrict__ bih2, const float* __restrict__ bhh2)
{
    __shared__ float sm[4160];
    const int tid = threadIdx.x;
    const int bid = blockIdx.x;
    const int gid = bid * NTHR + tid;
    const int gstride = NBLK * NTHR;   // 75776
    unsigned nb = 0;

    // ---------------- pre-stage: zero state ----------------
    for (int i = gid; i < 2*BB*H1S; i += gstride) ((float*)g_h1)[i] = 0.f;
    for (int i = gid; i < BB*H1S;   i += gstride) g_c1[i] = 0.f;
    for (int i = gid; i < 2*BB*KEY; i += gstride) ((float*)g_h2)[i] = 0.f;
    for (int i = gid; i < BB*KEY;   i += gstride) g_c2[i] = 0.f;
    for (int i = gid; i < BB*VAL;   i += gstride) g_ctx[i] = 0.f;

    // embedding gather: g_emb[(t*BB+b)*HID + h]
    for (int i = gid; i < T_DEC*BB*HID; i += gstride) {
        int h = i & (HID-1);
        int r = i >> 8;            // t*BB + b
        int b = r & (BB-1);
        int t = r >> 7;
        g_emb[i] = emb_table[text[b*T_DEC + t]*HID + h];
    }

    // convert K/V to fp16 (vectorized x4)
    {
        const int n4 = (T_ENC*BB*KEY) / 4;   // 8388608
        const float4* k4 = (const float4*)keys;
        const float4* v4 = (const float4*)values;
        __half2* kh2 = (__half2*)g_kh;
        __half2* vh2 = (__half2*)g_vh;
        for (int i = gid; i < n4; i += gstride) {
            float4 f = k4[i];
            kh2[2*i]   = __floats2half2_rn(f.x, f.y);
            kh2[2*i+1] = __floats2half2_rn(f.z, f.w);
            f = v4[i];
            vh2[2*i]   = __floats2half2_rn(f.x, f.y);
            vh2[2*i+1] = __floats2half2_rn(f.z, f.w);
        }
    }
    nb++; gbar(nb * NBLK);

    // ================= decode loop =================
    for (int t = 0; t < T_DEC; t++) {
        const int p = t & 1, pn = p ^ 1;

        // ---------- Stage A: gemm1 + cell1 ----------
        // gates1 = [emb_t(256) | ctx(128) | h1_prev(512)] @ W1^T  (K=896)
        // tile: 64 rows x (4 j x 4 gates = 16 cols). 256 tiles. split-K x4.
        if (bid < 256) {
            const int b0 = (bid >> 7) * 64;     // 0 or 64
            const int j0 = (bid & 127) * 4;     // 0..508
            const int q  = tid >> 6;            // k-quadrant 0..3 (224 k each)
            const int qt = tid & 63;
            const int r4 = (qt & 15) * 4;       // row offset in tile
            const int c4 = (qt >> 4) * 4;       // col offset in tile
            float acc[4][4];
            #pragma unroll
            for (int i = 0; i < 4; i++)
                #pragma unroll
                for (int j = 0; j < 4; j++) acc[i][j] = 0.f;

            float* As = sm;           // [4][8][64]
            float* Bs = sm + 2048;    // [4][8][16]

            for (int it = 0; it < 28; it++) {          // 28*8 = 224 per quadrant
                #pragma unroll
                for (int i = 0; i < 8; i++) {          // load A: 2048 floats
                    int li = i*256 + tid;
                    int lq = li >> 9, rem = li & 511;
                    int kk = rem >> 6, m = rem & 63;
                    int k = lq*224 + it*8 + kk;
                    int b = b0 + m;
                    float v;
                    if (k < HID)           v = g_emb[(t*BB + b)*HID + k];
                    else if (k < HID+VAL)  v = g_ctx[b*VAL + (k - HID)];
                    else                   v = g_h1[p][b*H1S + (k - HID - VAL)];
                    As[lq*512 + kk*64 + m] = v;
                }
                #pragma unroll
                for (int i = 0; i < 2; i++) {          // load B: 512 floats
                    int li = i*256 + tid;
                    int lq = li >> 7, rem = li & 127;
                    int kk = rem >> 4, ci = rem & 15;
                    int k = lq*224 + it*8 + kk;
                    int c = j0 + (ci & 3) + H1S*(ci >> 2);  // gate-grouped col
                    float v = (k < HID+VAL) ? Wih1[c*(HID+VAL) + k]
                                            : Whh1[c*H1S + (k - HID - VAL)];
                    Bs[lq*128 + kk*16 + ci] = v;
                }
                __syncthreads();
                #pragma unroll
                for (int kk = 0; kk < 8; kk++) {
                    float4 a  = *(float4*)&As[q*512 + kk*64 + r4];
                    float4 bq = *(float4*)&Bs[q*128 + kk*16 + c4];
                    float av[4] = {a.x, a.y, a.z, a.w};
                    float bv[4] = {bq.x, bq.y, bq.z, bq.w};
                    #pragma unroll
                    for (int i = 0; i < 4; i++)
                        #pragma unroll
                        for (int j = 0; j < 4; j++)
                            acc[i][j] += av[i] * bv[j];
                }
                __syncthreads();
            }
            // cross-quadrant reduce via smem
            float* red = sm;  // [4][1024], aliases As/Bs (safe after sync)
            #pragma unroll
            for (int i = 0; i < 4; i++)
                *(float4*)&red[q*1024 + (r4+i)*16 + c4] =
                    make_float4(acc[i][0], acc[i][1], acc[i][2], acc[i][3]);
            __syncthreads();
            // epilogue: 256 threads -> 64 rows x 4 j, fused LSTM1 cell
            {
                int r = tid & 63, jj = tid >> 6;
                float gsum[4];
                #pragma unroll
                for (int g = 0; g < 4; g++) {
                    float s = 0.f;
                    #pragma unroll
                    for (int qq = 0; qq < 4; qq++)
                        s += red[qq*1024 + r*16 + jj + 4*g];
                    gsum[g] = s;
                }
                int b = b0 + r, j = j0 + jj;
                float gi = gsum[0] + bih1[j]         + bhh1[j];
                float gf = gsum[1] + bih1[j +   H1S] + bhh1[j +   H1S];
                float gg = gsum[2] + bih1[j + 2*H1S] + bhh1[j + 2*H1S];
                float go = gsum[3] + bih1[j + 3*H1S] + bhh1[j + 3*H1S];
                int idx = b*H1S + j;
                float c = sigf(gf) * g_c1[idx] + sigf(gi) * tanhf(gg);
                g_c1[idx] = c;
                g_h1[pn][idx] = sigf(go) * tanhf(c);
            }
        }
        nb++; gbar(nb * NBLK);

        // ---------- Stage B: gemm2 + cell2 ----------
        // gates2 = [h1_new(512) | h2_prev(128)] @ W2^T  (K=640)
        // tile: 32 rows x (4 j x 4 gates = 16 cols). 128 tiles. split-K x4.
        if (bid < 128) {
            const int b0 = (bid >> 5) * 32;
            const int j0 = (bid & 31) * 4;
            const int q  = tid >> 6;          // 160 k per quadrant
            const int qt = tid & 63;
            const int r2 = (qt & 15) * 2;
            const int c4 = (qt >> 4) * 4;
            float acc[2][4];
            #pragma unroll
            for (int i = 0; i < 2; i++)
                #pragma unroll
                for (int j = 0; j < 4; j++) acc[i][j] = 0.f;

            float* As = sm;           // [4][8][32]
            float* Bs = sm + 1024;    // [4][8][16]

            for (int it = 0; it < 20; it++) {          // 20*8 = 160 per quadrant
                #pragma unroll
                for (int i = 0; i < 4; i++) {          // load A: 1024 floats
                    int li = i*256 + tid;
                    int lq = li >> 8, rem = li & 255;
                    int kk = rem >> 5, m = rem & 31;
                    int k = lq*160 + it*8 + kk;
                    int b = b0 + m;
                    float v = (k < H1S) ? g_h1[pn][b*H1S + k]
                                        : g_h2[p][b*KEY + (k - H1S)];
                    As[lq*256 + kk*32 + m] = v;
                }
                #pragma unroll
                for (int i = 0; i < 2; i++) {          // load B: 512 floats
                    int li = i*256 + tid;
                    int lq = li >> 7, rem = li & 127;
                    int kk = rem >> 4, ci = rem & 15;
                    int k = lq*160 + it*8 + kk;
                    int c = j0 + (ci & 3) + KEY*(ci >> 2);
                    float v = (k < H1S) ? Wih2[c*H1S + k]
                                        : Whh2[c*KEY + (k - H1S)];
                    Bs[lq*128 + kk*16 + ci] = v;
                }
                __syncthreads();
                #pragma unroll
                for (int kk = 0; kk < 8; kk++) {
                    float2 a  = *(float2*)&As[q*256 + kk*32 + r2];
                    float4 bq = *(float4*)&Bs[q*128 + kk*16 + c4];
                    float av[2] = {a.x, a.y};
                    float bv[4] = {bq.x, bq.y, bq.z, bq.w};
                    #pragma unroll
                    for (int i = 0; i < 2; i++)
                        #pragma unroll
                        for (int j = 0; j < 4; j++)
                            acc[i][j] += av[i] * bv[j];
                }
                __syncthreads();
            }
            float* red = sm;  // [4][512]
            #pragma unroll
            for (int i = 0; i < 2; i++)
                *(float4*)&red[q*512 + (r2+i)*16 + c4] =
                    make_float4(acc[i][0], acc[i][1], acc[i][2], acc[i][3]);
            __syncthreads();
            if (tid < 128) {   // 32 rows x 4 j
                int r = tid & 31, jj = tid >> 5;
                float gsum[4];
                #pragma unroll
                for (int g = 0; g < 4; g++) {
                    float s = 0.f;
                    #pragma unroll
                    for (int qq = 0; qq < 4; qq++)
                        s += red[qq*512 + r*16 + jj + 4*g];
                    gsum[g] = s;
                }
                int b = b0 + r, j = j0 + jj;
                float gi = gsum[0] + bih2[j]         + bhh2[j];
                float gf = gsum[1] + bih2[j +   KEY] + bhh2[j +   KEY];
                float gg = gsum[2] + bih2[j + 2*KEY] + bhh2[j + 2*KEY];
                float go = gsum[3] + bih2[j + 3*KEY] + bhh2[j + 3*KEY];
                int idx = b*KEY + j;
                float c = sigf(gf) * g_c2[idx] + sigf(gi) * tanhf(gg);
                g_c2[idx] = c;
                float h = sigf(go) * tanhf(c);
                g_h2[pn][idx] = h;
                g_h2ctx[((size_t)t*BB + b)*(KEY+VAL) + j] = h;
            }
        }
        nb++; gbar(nb * NBLK);

        // ---------- Stage C: attention (fp16 KV, online softmax) ----------
        if (bid < BB) {
            const int b = bid;
            const int lane = tid & 31, w = tid >> 5;   // 8 warps
            const float4 hq = *(const float4*)&g_h2[pn][b*KEY + lane*4];
            const int len = lens[b];

            float m = -3.0e38f, l = 0.f;
            float4 acc = {0.f, 0.f, 0.f, 0.f};

            for (int tt = w; tt < len; tt += 16) {
                uint2 ku1 = ((const uint2*)(g_kh + ((size_t)tt*BB + b)*KEY))[lane];
                uint2 vu1 = ((const uint2*)(g_vh + ((size_t)tt*BB + b)*VAL))[lane];
                bool has2 = (tt + 8 < len);
                uint2 ku2, vu2;
                if (has2) {
                    ku2 = ((const uint2*)(g_kh + ((size_t)(tt+8)*BB + b)*KEY))[lane];
                    vu2 = ((const uint2*)(g_vh + ((size_t)(tt+8)*BB + b)*VAL))[lane];
                }
                // --- tt ---
                {
                    float4 kf = h4tof4(ku1);
                    float e = kf.x*hq.x + kf.y*hq.y + kf.z*hq.z + kf.w*hq.w;
                    #pragma unroll
                    for (int off = 16; off; off >>= 1) e += __shfl_xor_sync(~0u, e, off);
                    float4 vf = h4tof4(vu1);
                    float mn = fmaxf(m, e);
                    float sc = expf(m - mn);
                    float pw = expf(e - mn);
                    l = l*sc + pw;
                    acc.x = acc.x*sc + pw*vf.x; acc.y = acc.y*sc + pw*vf.y;
                    acc.z = acc.z*sc + pw*vf.z; acc.w = acc.w*sc + pw*vf.w;
                    m = mn;
                }
                // --- tt + 8 ---
                if (has2) {
                    float4 kf = h4tof4(ku2);
                    float e = kf.x*hq.x + kf.y*hq.y + kf.z*hq.z + kf.w*hq.w;
                    #pragma unroll
                    for (int off = 16; off; off >>= 1) e += __shfl_xor_sync(~0u, e, off);
                    float4 vf = h4tof4(vu2);
                    float mn = fmaxf(m, e);
                    float sc = expf(m - mn);
                    float pw = expf(e - mn);
                    l = l*sc + pw;
                    acc.x = acc.x*sc + pw*vf.x; acc.y = acc.y*sc + pw*vf.y;
                    acc.z = acc.z*sc + pw*vf.z; acc.w = acc.w*sc + pw*vf.w;
                    m = mn;
                }
            }

            float* s_acc = sm;               // [8][128]
            float* s_m = sm + 1024;          // [8]
            float* s_l = sm + 1032;          // [8]
            float* s_f = sm + 1040;          // [8]
            *(float4*)&s_acc[w*128 + lane*4] = acc;
            if (lane == 0) { s_m[w] = m; s_l[w] = l; }
            __syncthreads();
            float M = -3.0e38f;
            #pragma unroll
            for (int ww = 0; ww < 8; ww++) M = fmaxf(M, s_m[ww]);
            if (tid < 8) s_f[tid] = expf(s_m[tid] - M);
            __syncthreads();
            if (tid < 128) {
                float L = 0.f, s = 0.f;
                #pragma unroll
                for (int ww = 0; ww < 8; ww++) {
                    L += s_l[ww] * s_f[ww];
                    s += s_acc[ww*128 + tid] * s_f[ww];
                }
                float cx = s / L;
                g_ctx[b*VAL + tid] = cx;
                g_h2ctx[((size_t)t*BB + b)*(KEY+VAL) + KEY + tid] = cx;
            }
        }
        nb++; gbar(nb * NBLK);
    }
}

// ---------------- final logits GEMM (batched over all steps) -------------
// C (32768 x 1000) = h2ctx (32768 x 256) @ Wlin^T, tile 64x64, BK=16
__global__ __launch_bounds__(256) void pred_kernel(
    const float* __restrict__ Wlin, const float* __restrict__ blin,
    float* __restrict__ out)
{
    __shared__ float As[16][68];
    __shared__ float Bs[16][68];
    const int r0 = blockIdx.x * 64;
    const int v0 = blockIdx.y * 64;
    const int tid = threadIdx.x;
    const int m0 = (tid & 15) * 4;
    const int n0 = (tid >> 4) * 4;
    float acc[4][4] = {};

    for (int k0 = 0; k0 < 256; k0 += 16) {
        #pragma unroll
        for (int i = 0; i < 4; i++) {
            int li = i*256 + tid;
            int m = li >> 4, kk = li & 15;
            As[kk][m] = g_h2ctx[(size_t)(r0 + m)*256 + k0 + kk];
        }
        #pragma unroll
        for (int i = 0; i < 4; i++) {
            int li = i*256 + tid;
            int n = li >> 4, kk = li & 15;
            int v = v0 + n;
            Bs[kk][n] = (v < VOCAB) ? Wlin[v*256 + k0 + kk] : 0.f;
        }
        __syncthreads();
        #pragma unroll
        for (int kk = 0; kk < 16; kk++) {
            float4 a = *(const float4*)&As[kk][m0];
            float4 bq = *(const float4*)&Bs[kk][n0];
            float av[4] = {a.x, a.y, a.z, a.w};
            float bv[4] = {bq.x, bq.y, bq.z, bq.w};
            #pragma unroll
            for (int i = 0; i < 4; i++)
                #pragma unroll
                for (int j = 0; j < 4; j++)
                    acc[i][j] += av[i] * bv[j];
        }
        __syncthreads();
    }
    #pragma unroll
    for (int i = 0; i < 4; i++) {
        int r = r0 + m0 + i;
        int b = r & 127, t = r >> 7;
        #pragma unroll
        for (int j = 0; j < 4; j++) {
            int v = v0 + n0 + j;
            if (v < VOCAB)
                out[((size_t)b*T_DEC + t)*VOCAB + v] = acc[i][j] + blin[v];
        }
    }
}

// ---------------- launch ----------------
extern "C" void kernel_launch(void* const* d_in, const int* in_sizes, int n_in,
                              void* d_out, int out_size)
{
    const float* keys      = (const float*)d_in[0];
    const float* values    = (const float*)d_in[1];
    const int*   lens      = (const int*)  d_in[2];
    const int*   text      = (const int*)  d_in[3];
    const float* emb_table = (const float*)d_in[4];
    const float* Wih1      = (const float*)d_in[5];
    const float* Whh1      = (const float*)d_in[6];
    const float* bih1      = (const float*)d_in[7];
    const float* bhh1      = (const float*)d_in[8];
    const float* Wih2      = (const float*)d_in[9];
    const float* Whh2      = (const float*)d_in[10];
    const float* bih2      = (const float*)d_in[11];
    const float* bhh2      = (const float*)d_in[12];
    const float* Wlin      = (const float*)d_in[13];
    const float* blin      = (const float*)d_in[14];
    float* out = (float*)d_out;

    reset_bar_kernel<<<1, 1>>>();
    decoder_kernel<<<NBLK, NTHR>>>(keys, values, lens, text, emb_table,
                                   Wih1, Whh1, bih1, bhh1,
                                   Wih2, Whh2, bih2, bhh2);
    pred_kernel<<<dim3((T_DEC*BB)/64, (VOCAB + 63)/64), 256>>>(Wlin, blin, out);
}

// round 8
// speedup vs baseline: 1.8920x; 1.8920x over previous
#include <cuda_runtime.h>
#include <cuda_fp16.h>
#include <math.h>

#define BB 128       // batch
#define T_ENC 2048
#define T_DEC 256
#define HID 256
#define KEY 128
#define VAL 128
#define H1S 512      // lstm1 hidden
#define VOCAB 1000
#define NBLK 296     // 2 CTAs/SM * 148 SMs, all resident
#define NTHR 256
#define NROWS (T_DEC*BB)   // 32768

// ---------------- device scratch (static) ----------------
__device__ unsigned g_bar;
__device__ float g_embT[(size_t)T_DEC*HID*BB];          // [t][h][b]
__device__ float g_h2ctxT[(size_t)(KEY+VAL)*NROWS];     // [f][t*BB+b]
__device__ float g_h1T[2][H1S*BB];                      // [j][b]
__device__ float g_c1T[H1S*BB];
__device__ float g_h2T[2][KEY*BB];
__device__ float g_c2T[KEY*BB];
__device__ float g_ctxT[VAL*BB];                        // [v][b]
__device__ float g_W1p[(size_t)128*896*16];             // [tile][k][16]
__device__ float g_W2p[(size_t)32*640*16];
__device__ __align__(16) __half g_kh[(size_t)T_ENC*BB*KEY];
__device__ __align__(16) __half g_vh[(size_t)T_ENC*BB*VAL];

// ---------------- global software barrier (monotonic counter) ------------
__device__ __forceinline__ void gbar(unsigned target) {
    __syncthreads();
    if (threadIdx.x == 0) {
        __threadfence();
        atomicAdd(&g_bar, 1u);
        while (*(volatile unsigned*)&g_bar < target) __nanosleep(64);
        __threadfence();
    }
    __syncthreads();
}

__global__ void reset_bar_kernel() { g_bar = 0u; }

__device__ __forceinline__ float sigf(float x) { return 1.f / (1.f + expf(-x)); }

__device__ __forceinline__ float4 h4tof4(uint2 u) {
    __half2 a = *(__half2*)&u.x;
    __half2 b = *(__half2*)&u.y;
    float2 fa = __half22float2(a), fb = __half22float2(b);
    return make_float4(fa.x, fa.y, fb.x, fb.y);
}

// =============================================================================
// Persistent decoder kernel
// =============================================================================
__global__ __launch_bounds__(NTHR, 2) void decoder_kernel(
    const float* __restrict__ keys, const float* __restrict__ values,
    const int* __restrict__ lens, const int* __restrict__ text,
    const float* __restrict__ emb_table,
    const float* __restrict__ Wih1, const float* __restrict__ Whh1,
    const float* __restrict__ bih1, const float* __restrict__ bhh1,
    const float* __restrict__ Wih2, const float* __restrict__ Whh2,
    const float* __restrict__ bih2, const float* __restrict__ bhh2)
{
    __shared__ float sm[4160];
    const int tid = threadIdx.x;
    const int bid = blockIdx.x;
    const int gid = bid * NTHR + tid;
    const int gstride = NBLK * NTHR;   // 75776
    unsigned nb = 0;

    // ---------------- pre-stage ----------------
    for (int i = gid; i < 2*H1S*BB; i += gstride) ((float*)g_h1T)[i] = 0.f;
    for (int i = gid; i < H1S*BB;   i += gstride) g_c1T[i] = 0.f;
    for (int i = gid; i < 2*KEY*BB; i += gstride) ((float*)g_h2T)[i] = 0.f;
    for (int i = gid; i < KEY*BB;   i += gstride) g_c2T[i] = 0.f;
    for (int i = gid; i < VAL*BB;   i += gstride) g_ctxT[i] = 0.f;

    // embedding gather -> [t][h][b]  (writes coalesced; table reads hit L2)
    for (int i = gid; i < T_DEC*HID*BB; i += gstride) {
        int b = i & (BB-1);
        int f = i >> 7;
        int h = f & (HID-1);
        int t = f >> 8;
        g_embT[i] = emb_table[text[b*T_DEC + t]*HID + h];
    }

    // pack W1 -> [128 tiles][896 k][16 cols] (gate-grouped)
    for (int i = gid; i < 128*896*16; i += gstride) {
        int ci = i & 15;
        int k  = (i >> 4) % 896;
        int n  = i / (896*16);
        int c  = n*4 + (ci & 3) + H1S * (ci >> 2);
        g_W1p[i] = (k < HID+VAL) ? Wih1[c*(HID+VAL) + k]
                                 : Whh1[c*H1S + (k - HID - VAL)];
    }
    // pack W2 -> [32 tiles][640 k][16 cols]
    for (int i = gid; i < 32*640*16; i += gstride) {
        int ci = i & 15;
        int k  = (i >> 4) % 640;
        int n  = i / (640*16);
        int c  = n*4 + (ci & 3) + KEY * (ci >> 2);
        g_W2p[i] = (k < H1S) ? Wih2[c*H1S + k] : Whh2[c*KEY + (k - H1S)];
    }

    // convert K/V to fp16
    {
        const int n4 = (T_ENC*BB*KEY) / 4;
        const float4* k4 = (const float4*)keys;
        const float4* v4 = (const float4*)values;
        __half2* kh2 = (__half2*)g_kh;
        __half2* vh2 = (__half2*)g_vh;
        for (int i = gid; i < n4; i += gstride) {
            float4 f = k4[i];
            kh2[2*i]   = __floats2half2_rn(f.x, f.y);
            kh2[2*i+1] = __floats2half2_rn(f.z, f.w);
            f = v4[i];
            vh2[2*i]   = __floats2half2_rn(f.x, f.y);
            vh2[2*i+1] = __floats2half2_rn(f.z, f.w);
        }
    }
    nb++; gbar(nb * NBLK);

    // ================= decode loop =================
    for (int t = 0; t < T_DEC; t++) {
        const int p = t & 1, pn = p ^ 1;

        // ---------- Stage A: gemm1 + cell1 ----------
        // gates1 = [embT|ctxT|h1T_prev] (k-major) @ W1p, K=896
        // tile 64 rows x 16 cols (4j x 4gates), 256 blocks, split-K x4 in-block
        if (bid < 256) {
            const int b0 = (bid >> 7) * 64;
            const int n  = bid & 127;
            const int j0 = n * 4;
            const int q  = tid >> 6;          // k-quadrant (224 k each)
            const int qt = tid & 63;
            const int r4 = (qt & 15) * 4;
            const int c4 = (qt >> 4) * 4;
            const float* Wp = g_W1p + (size_t)n * (896*16);
            float acc[4][4];
            #pragma unroll
            for (int i = 0; i < 4; i++)
                #pragma unroll
                for (int j = 0; j < 4; j++) acc[i][j] = 0.f;

            float* As = sm;           // [4][8][64]
            float* Bs = sm + 2048;    // [4][8][16]

            for (int it = 0; it < 28; it++) {
                #pragma unroll
                for (int i = 0; i < 8; i++) {      // A: coalesced over m
                    int li = i*256 + tid;
                    int lq = li >> 9, rem = li & 511;
                    int kk = rem >> 6, m = rem & 63;
                    int k = lq*224 + it*8 + kk;
                    int b = b0 + m;
                    float v;
                    if (k < HID)          v = g_embT[((size_t)t*HID + k)*BB + b];
                    else if (k < HID+VAL) v = g_ctxT[(k - HID)*BB + b];
                    else                  v = g_h1T[p][(k - HID - VAL)*BB + b];
                    As[lq*512 + kk*64 + m] = v;
                }
                #pragma unroll
                for (int i = 0; i < 2; i++) {      // B: coalesced (packed)
                    int li = i*256 + tid;
                    int lq = li >> 7, rem = li & 127;
                    int kk = rem >> 4, ci = rem & 15;
                    int k = lq*224 + it*8 + kk;
                    Bs[lq*128 + kk*16 + ci] = Wp[k*16 + ci];
                }
                __syncthreads();
                #pragma unroll
                for (int kk = 0; kk < 8; kk++) {
                    float4 a  = *(float4*)&As[q*512 + kk*64 + r4];
                    float4 bq = *(float4*)&Bs[q*128 + kk*16 + c4];
                    float av[4] = {a.x, a.y, a.z, a.w};
                    float bv[4] = {bq.x, bq.y, bq.z, bq.w};
                    #pragma unroll
                    for (int i = 0; i < 4; i++)
                        #pragma unroll
                        for (int j = 0; j < 4; j++)
                            acc[i][j] += av[i] * bv[j];
                }
                __syncthreads();
            }
            float* red = sm;  // [4][1024]
            #pragma unroll
            for (int i = 0; i < 4; i++)
                *(float4*)&red[q*1024 + (r4+i)*16 + c4] =
                    make_float4(acc[i][0], acc[i][1], acc[i][2], acc[i][3]);
            __syncthreads();
            {   // fused LSTM1 cell epilogue: 64 rows x 4 j
                int r = tid & 63, jj = tid >> 6;
                float gsum[4];
                #pragma unroll
                for (int g = 0; g < 4; g++) {
                    float s = 0.f;
                    #pragma unroll
                    for (int qq = 0; qq < 4; qq++)
                        s += red[qq*1024 + r*16 + jj + 4*g];
                    gsum[g] = s;
                }
                int b = b0 + r, j = j0 + jj;
                float gi = gsum[0] + bih1[j]         + bhh1[j];
                float gf = gsum[1] + bih1[j +   H1S] + bhh1[j +   H1S];
                float gg = gsum[2] + bih1[j + 2*H1S] + bhh1[j + 2*H1S];
                float go = gsum[3] + bih1[j + 3*H1S] + bhh1[j + 3*H1S];
                int idx = j*BB + b;    // transposed, coalesced over r
                float c = sigf(gf) * g_c1T[idx] + sigf(gi) * tanhf(gg);
                g_c1T[idx] = c;
                g_h1T[pn][idx] = sigf(go) * tanhf(c);
            }
        }
        nb++; gbar(nb * NBLK);

        // ---------- Stage B: gemm2 + cell2 ----------
        // gates2 = [h1T_new|h2T_prev] @ W2p, K=640
        // tile 32 rows x 16 cols, 128 blocks, split-K x4 in-block
        if (bid < 128) {
            const int b0 = (bid >> 5) * 32;
            const int n  = bid & 31;
            const int j0 = n * 4;
            const int q  = tid >> 6;          // 160 k per quadrant
            const int qt = tid & 63;
            const int r2 = (qt & 15) * 2;
            const int c4 = (qt >> 4) * 4;
            const float* Wp = g_W2p + (size_t)n * (640*16);
            float acc[2][4];
            #pragma unroll
            for (int i = 0; i < 2; i++)
                #pragma unroll
                for (int j = 0; j < 4; j++) acc[i][j] = 0.f;

            float* As = sm;           // [4][8][32]
            float* Bs = sm + 1024;    // [4][8][16]

            for (int it = 0; it < 20; it++) {
                #pragma unroll
                for (int i = 0; i < 4; i++) {      // A: coalesced over m
                    int li = i*256 + tid;
                    int lq = li >> 8, rem = li & 255;
                    int kk = rem >> 5, m = rem & 31;
                    int k = lq*160 + it*8 + kk;
                    int b = b0 + m;
                    float v = (k < H1S) ? g_h1T[pn][k*BB + b]
                                        : g_h2T[p][(k - H1S)*BB + b];
                    As[lq*256 + kk*32 + m] = v;
                }
                #pragma unroll
                for (int i = 0; i < 2; i++) {      // B: coalesced (packed)
                    int li = i*256 + tid;
                    int lq = li >> 7, rem = li & 127;
                    int kk = rem >> 4, ci = rem & 15;
                    int k = lq*160 + it*8 + kk;
                    Bs[lq*128 + kk*16 + ci] = Wp[k*16 + ci];
                }
                __syncthreads();
                #pragma unroll
                for (int kk = 0; kk < 8; kk++) {
                    float2 a  = *(float2*)&As[q*256 + kk*32 + r2];
                    float4 bq = *(float4*)&Bs[q*128 + kk*16 + c4];
                    float av[2] = {a.x, a.y};
                    float bv[4] = {bq.x, bq.y, bq.z, bq.w};
                    #pragma unroll
                    for (int i = 0; i < 2; i++)
                        #pragma unroll
                        for (int j = 0; j < 4; j++)
                            acc[i][j] += av[i] * bv[j];
                }
                __syncthreads();
            }
            float* red = sm;  // [4][512]
            #pragma unroll
            for (int i = 0; i < 2; i++)
                *(float4*)&red[q*512 + (r2+i)*16 + c4] =
                    make_float4(acc[i][0], acc[i][1], acc[i][2], acc[i][3]);
            __syncthreads();
            if (tid < 128) {   // 32 rows x 4 j
                int r = tid & 31, jj = tid >> 5;
                float gsum[4];
                #pragma unroll
                for (int g = 0; g < 4; g++) {
                    float s = 0.f;
                    #pragma unroll
                    for (int qq = 0; qq < 4; qq++)
                        s += red[qq*512 + r*16 + jj + 4*g];
                    gsum[g] = s;
                }
                int b = b0 + r, j = j0 + jj;
                float gi = gsum[0] + bih2[j]         + bhh2[j];
                float gf = gsum[1] + bih2[j +   KEY] + bhh2[j +   KEY];
                float gg = gsum[2] + bih2[j + 2*KEY] + bhh2[j + 2*KEY];
                float go = gsum[3] + bih2[j + 3*KEY] + bhh2[j + 3*KEY];
                int idx = j*BB + b;
                float c = sigf(gf) * g_c2T[idx] + sigf(gi) * tanhf(gg);
                g_c2T[idx] = c;
                float h = sigf(go) * tanhf(c);
                g_h2T[pn][idx] = h;
                g_h2ctxT[(size_t)j*NROWS + t*BB + b] = h;  // coalesced over r
            }
        }
        nb++; gbar(nb * NBLK);

        // ---------- Stage C: attention (fp16 KV, online softmax) ----------
        if (bid < BB) {
            const int b = bid;
            const int lane = tid & 31, w = tid >> 5;   // 8 warps
            float* s_h2 = sm + 1152;
            if (tid < 128) s_h2[tid] = g_h2T[pn][tid*BB + b];
            __syncthreads();
            const float4 hq = *(float4*)&s_h2[lane*4];
            const int len = lens[b];

            float m = -3.0e38f, l = 0.f;
            float4 acc = {0.f, 0.f, 0.f, 0.f};

            for (int tt = w; tt < len; tt += 16) {
                uint2 ku1 = ((const uint2*)(g_kh + ((size_t)tt*BB + b)*KEY))[lane];
                uint2 vu1 = ((const uint2*)(g_vh + ((size_t)tt*BB + b)*VAL))[lane];
                bool has2 = (tt + 8 < len);
                uint2 ku2, vu2;
                if (has2) {
                    ku2 = ((const uint2*)(g_kh + ((size_t)(tt+8)*BB + b)*KEY))[lane];
                    vu2 = ((const uint2*)(g_vh + ((size_t)(tt+8)*BB + b)*VAL))[lane];
                }
                {
                    float4 kf = h4tof4(ku1);
                    float e = kf.x*hq.x + kf.y*hq.y + kf.z*hq.z + kf.w*hq.w;
                    #pragma unroll
                    for (int off = 16; off; off >>= 1) e += __shfl_xor_sync(~0u, e, off);
                    float4 vf = h4tof4(vu1);
                    float mn = fmaxf(m, e);
                    float sc = expf(m - mn);
                    float pw = expf(e - mn);
                    l = l*sc + pw;
                    acc.x = acc.x*sc + pw*vf.x; acc.y = acc.y*sc + pw*vf.y;
                    acc.z = acc.z*sc + pw*vf.z; acc.w = acc.w*sc + pw*vf.w;
                    m = mn;
                }
                if (has2) {
                    float4 kf = h4tof4(ku2);
                    float e = kf.x*hq.x + kf.y*hq.y + kf.z*hq.z + kf.w*hq.w;
                    #pragma unroll
                    for (int off = 16; off; off >>= 1) e += __shfl_xor_sync(~0u, e, off);
                    float4 vf = h4tof4(vu2);
                    float mn = fmaxf(m, e);
                    float sc = expf(m - mn);
                    float pw = expf(e - mn);
                    l = l*sc + pw;
                    acc.x = acc.x*sc + pw*vf.x; acc.y = acc.y*sc + pw*vf.y;
                    acc.z = acc.z*sc + pw*vf.z; acc.w = acc.w*sc + pw*vf.w;
                    m = mn;
                }
            }

            float* s_acc = sm;               // [8][128]
            float* s_m = sm + 1024;
            float* s_l = sm + 1032;
            float* s_f = sm + 1040;
            *(float4*)&s_acc[w*128 + lane*4] = acc;
            if (lane == 0) { s_m[w] = m; s_l[w] = l; }
            __syncthreads();
            float M = -3.0e38f;
            #pragma unroll
            for (int ww = 0; ww < 8; ww++) M = fmaxf(M, s_m[ww]);
            if (tid < 8) s_f[tid] = expf(s_m[tid] - M);
            __syncthreads();
            if (tid < 128) {
                float L = 0.f, s = 0.f;
                #pragma unroll
                for (int ww = 0; ww < 8; ww++) {
                    L += s_l[ww] * s_f[ww];
                    s += s_acc[ww*128 + tid] * s_f[ww];
                }
                float cx = s / L;
                g_ctxT[tid*BB + b] = cx;
                g_h2ctxT[(size_t)(KEY + tid)*NROWS + t*BB + b] = cx;
            }
        }
        nb++; gbar(nb * NBLK);
    }
}

// ---------------- final logits GEMM -------------
// C (32768 x 1000) = h2ctxT^T (32768 x 256) @ Wlin^T, tile 64x64, BK=16
__global__ __launch_bounds__(256) void pred_kernel(
    const float* __restrict__ Wlin, const float* __restrict__ blin,
    float* __restrict__ out)
{
    __shared__ float As[16][68];
    __shared__ float Bs[16][68];
    const int r0 = blockIdx.x * 64;
    const int v0 = blockIdx.y * 64;
    const int tid = threadIdx.x;
    const int m0 = (tid & 15) * 4;
    const int n0 = (tid >> 4) * 4;
    float acc[4][4] = {};

    for (int k0 = 0; k0 < 256; k0 += 16) {
        #pragma unroll
        for (int i = 0; i < 4; i++) {     // A: coalesced over m
            int li = i*256 + tid;
            int kk = li >> 6, m = li & 63;
            As[kk][m] = g_h2ctxT[(size_t)(k0 + kk)*NROWS + r0 + m];
        }
        #pragma unroll
        for (int i = 0; i < 4; i++) {
            int li = i*256 + tid;
            int n = li >> 4, kk = li & 15;
            int v = v0 + n;
            Bs[kk][n] = (v < VOCAB) ? Wlin[v*256 + k0 + kk] : 0.f;
        }
        __syncthreads();
        #pragma unroll
        for (int kk = 0; kk < 16; kk++) {
            float4 a = *(const float4*)&As[kk][m0];
            float4 bq = *(const float4*)&Bs[kk][n0];
            float av[4] = {a.x, a.y, a.z, a.w};
            float bv[4] = {bq.x, bq.y, bq.z, bq.w};
            #pragma unroll
            for (int i = 0; i < 4; i++)
                #pragma unroll
                for (int j = 0; j < 4; j++)
                    acc[i][j] += av[i] * bv[j];
        }
        __syncthreads();
    }
    #pragma unroll
    for (int i = 0; i < 4; i++) {
        int r = r0 + m0 + i;
        int b = r & 127, t = r >> 7;
        #pragma unroll
        for (int j = 0; j < 4; j++) {
            int v = v0 + n0 + j;
            if (v < VOCAB)
                out[((size_t)b*T_DEC + t)*VOCAB + v] = acc[i][j] + blin[v];
        }
    }
}

// ---------------- launch ----------------
extern "C" void kernel_launch(void* const* d_in, const int* in_sizes, int n_in,
                              void* d_out, int out_size)
{
    const float* keys      = (const float*)d_in[0];
    const float* values    = (const float*)d_in[1];
    const int*   lens      = (const int*)  d_in[2];
    const int*   text      = (const int*)  d_in[3];
    const float* emb_table = (const float*)d_in[4];
    const float* Wih1      = (const float*)d_in[5];
    const float* Whh1      = (const float*)d_in[6];
    const float* bih1      = (const float*)d_in[7];
    const float* bhh1      = (const float*)d_in[8];
    const float* Wih2      = (const float*)d_in[9];
    const float* Whh2      = (const float*)d_in[10];
    const float* bih2      = (const float*)d_in[11];
    const float* bhh2      = (const float*)d_in[12];
    const float* Wlin      = (const float*)d_in[13];
    const float* blin      = (const float*)d_in[14];
    float* out = (float*)d_out;

    reset_bar_kernel<<<1, 1>>>();
    decoder_kernel<<<NBLK, NTHR>>>(keys, values, lens, text, emb_table,
                                   Wih1, Whh1, bih1, bhh1,
                                   Wih2, Whh2, bih2, bhh2);
    pred_kernel<<<dim3(NROWS/64, (VOCAB + 63)/64), 256>>>(Wlin, blin, out);
}

// round 9
// speedup vs baseline: 3.4208x; 1.8080x over previous
#include <cuda_runtime.h>
#include <cuda_fp16.h>
#include <math.h>

#define BB 128       // batch
#define T_ENC 2048
#define T_DEC 256
#define HID 256
#define KEY 128
#define VAL 128
#define H1S 512      // lstm1 hidden
#define VOCAB 1000
#define NBLK 296     // 2 CTAs/SM * 148 SMs, all resident
#define NTHR 256
#define NROWS (T_DEC*BB)   // 32768

// ---------------- device scratch (static) ----------------
__device__ unsigned g_leaf[8*64];   // 8 leaf counters, 256B apart
__device__ unsigned g_root;
__device__ float g_embT[(size_t)T_DEC*HID*BB];          // [t][h][b]
__device__ float g_h2ctxT[(size_t)(KEY+VAL)*NROWS];     // [f][t*BB+b]
__device__ float g_h1T[2][H1S*BB];                      // [j][b]
__device__ float g_c1T[H1S*BB];
__device__ float g_h2T[2][KEY*BB];
__device__ float g_c2T[KEY*BB];
__device__ float g_ctxT[VAL*BB];                        // [v][b]
__device__ float g_W1p[(size_t)128*896*16];             // [tile][k][16]
__device__ float g_W2p[(size_t)32*640*16];
__device__ __align__(16) __half g_khT[(size_t)BB*KEY*T_ENC];  // [b][k][t]
__device__ __align__(16) __half g_vh[(size_t)T_ENC*BB*VAL];   // [t][b][v]

// ---------------- hierarchical global barrier (monotonic) ----------------
__device__ __forceinline__ void gbar(int bid, unsigned ph) {
    __syncthreads();
    if (threadIdx.x == 0) {
        __threadfence();
        int g = bid & 7;                       // 37 blocks per leaf (296 = 8*37)
        unsigned old = atomicAdd(&g_leaf[g*64], 1u);
        if (old == ph*37u - 1u) atomicAdd(&g_root, 1u);
        while (*(volatile unsigned*)&g_root < ph*8u) __nanosleep(32);
        __threadfence();
    }
    __syncthreads();
}

__global__ void reset_bar_kernel() {
    int i = threadIdx.x;
    if (i < 8*64) g_leaf[i] = 0u;
    if (i == 0) g_root = 0u;
}

__device__ __forceinline__ float sigf(float x) { return 1.f / (1.f + expf(-x)); }

// =============================================================================
// Persistent decoder kernel
// =============================================================================
__global__ __launch_bounds__(NTHR, 2) void decoder_kernel(
    const float* __restrict__ keys, const float* __restrict__ values,
    const int* __restrict__ lens, const int* __restrict__ text,
    const float* __restrict__ emb_table,
    const float* __restrict__ Wih1, const float* __restrict__ Whh1,
    const float* __restrict__ bih1, const float* __restrict__ bhh1,
    const float* __restrict__ Wih2, const float* __restrict__ Whh2,
    const float* __restrict__ bih2, const float* __restrict__ bhh2)
{
    __shared__ float sm[4160];
    const int tid = threadIdx.x;
    const int bid = blockIdx.x;
    const int gid = bid * NTHR + tid;
    const int gstride = NBLK * NTHR;   // 75776
    unsigned nb = 0;

    // ---------------- pre-stage ----------------
    for (int i = gid; i < 2*H1S*BB; i += gstride) ((float*)g_h1T)[i] = 0.f;
    for (int i = gid; i < H1S*BB;   i += gstride) g_c1T[i] = 0.f;
    for (int i = gid; i < 2*KEY*BB; i += gstride) ((float*)g_h2T)[i] = 0.f;
    for (int i = gid; i < KEY*BB;   i += gstride) g_c2T[i] = 0.f;
    for (int i = gid; i < VAL*BB;   i += gstride) g_ctxT[i] = 0.f;

    // embedding gather -> [t][h][b]
    for (int i = gid; i < T_DEC*HID*BB; i += gstride) {
        int b = i & (BB-1);
        int f = i >> 7;
        int h = f & (HID-1);
        int t = f >> 8;
        g_embT[i] = emb_table[text[b*T_DEC + t]*HID + h];
    }

    // pack W1 -> [128 tiles][896 k][16 cols] (gate-grouped)
    for (int i = gid; i < 128*896*16; i += gstride) {
        int ci = i & 15;
        int k  = (i >> 4) % 896;
        int n  = i / (896*16);
        int c  = n*4 + (ci & 3) + H1S * (ci >> 2);
        g_W1p[i] = (k < HID+VAL) ? Wih1[c*(HID+VAL) + k]
                                 : Whh1[c*H1S + (k - HID - VAL)];
    }
    // pack W2 -> [32 tiles][640 k][16 cols]
    for (int i = gid; i < 32*640*16; i += gstride) {
        int ci = i & 15;
        int k  = (i >> 4) % 640;
        int n  = i / (640*16);
        int c  = n*4 + (ci & 3) + KEY * (ci >> 2);
        g_W2p[i] = (k < H1S) ? Wih2[c*H1S + k] : Whh2[c*KEY + (k - H1S)];
    }

    // convert V to fp16 ([t][b][v] layout kept)
    {
        const int n4 = (T_ENC*BB*VAL) / 4;
        const float4* v4 = (const float4*)values;
        __half2* vh2 = (__half2*)g_vh;
        for (int i = gid; i < n4; i += gstride) {
            float4 f = v4[i];
            vh2[2*i]   = __floats2half2_rn(f.x, f.y);
            vh2[2*i+1] = __floats2half2_rn(f.z, f.w);
        }
    }

    // transpose K -> fp16 [b][k][t] via smem tiles (64 t x 32 k per job)
    for (int j = bid; j < 128*4*32; j += NBLK) {
        int b  = j >> 7;          // 0..127
        int kt = (j >> 5) & 3;    // 0..3   (k tile of 32)
        int tt = j & 31;          // 0..31  (t tile of 64)
        float* st = sm;           // [64][33]
        #pragma unroll
        for (int p8 = 0; p8 < 8; p8++) {
            int trow = p8*8 + (tid >> 5);
            int kcol = tid & 31;
            st[trow*33 + kcol] =
                keys[((size_t)(tt*64 + trow)*BB + b)*KEY + kt*32 + kcol];
        }
        __syncthreads();
        #pragma unroll
        for (int p4 = 0; p4 < 8; p4++) {
            int kr   = p4*4 + (tid >> 6);
            int tcol = tid & 63;
            g_khT[((size_t)b*KEY + kt*32 + kr)*T_ENC + tt*64 + tcol] =
                __float2half_rn(st[tcol*33 + kr]);
        }
        __syncthreads();
    }
    nb++; gbar(bid, nb);

    // ================= decode loop =================
    for (int t = 0; t < T_DEC; t++) {
        const int p = t & 1, pn = p ^ 1;

        // ---------- Stage A: gemm1 + cell1 (register-prefetch pipelined) ----
        if (bid < 256) {
            const int b0 = (bid >> 7) * 64;
            const int n  = bid & 127;
            const int j0 = n * 4;
            const int q  = tid >> 6;          // k-quadrant (224 k each)
            const int qt = tid & 63;
            const int r4 = (qt & 15) * 4;
            const int c4 = (qt >> 4) * 4;
            const float* Wp = g_W1p + (size_t)n * (896*16);
            float acc[4][4];
            #pragma unroll
            for (int i = 0; i < 4; i++)
                #pragma unroll
                for (int j = 0; j < 4; j++) acc[i][j] = 0.f;

            float* As = sm;           // [4][8][64]
            float* Bs = sm + 2048;    // [4][8][16]
            float ra[8], rb[2];

            // prefetch iter 0
            #pragma unroll
            for (int i = 0; i < 8; i++) {
                int li = i*256 + tid;
                int k = (li >> 9)*224 + ((li >> 6) & 7);
                int b = b0 + (li & 63);
                ra[i] = (k < HID) ? g_embT[((size_t)t*HID + k)*BB + b]
                      : (k < HID+VAL) ? g_ctxT[(k - HID)*BB + b]
                      : g_h1T[p][(k - HID - VAL)*BB + b];
            }
            #pragma unroll
            for (int i = 0; i < 2; i++) {
                int li = i*256 + tid;
                int k = (li >> 7)*224 + ((li >> 4) & 7);
                rb[i] = Wp[k*16 + (li & 15)];
            }

            for (int it = 0; it < 28; it++) {
                #pragma unroll
                for (int i = 0; i < 8; i++) {
                    int li = i*256 + tid;
                    As[(li >> 9)*512 + ((li >> 6) & 7)*64 + (li & 63)] = ra[i];
                }
                #pragma unroll
                for (int i = 0; i < 2; i++) {
                    int li = i*256 + tid;
                    Bs[(li >> 7)*128 + ((li >> 4) & 7)*16 + (li & 15)] = rb[i];
                }
                __syncthreads();
                if (it < 27) {   // issue next iter's loads (latency hidden by compute)
                    #pragma unroll
                    for (int i = 0; i < 8; i++) {
                        int li = i*256 + tid;
                        int k = (li >> 9)*224 + (it+1)*8 + ((li >> 6) & 7);
                        int b = b0 + (li & 63);
                        ra[i] = (k < HID) ? g_embT[((size_t)t*HID + k)*BB + b]
                              : (k < HID+VAL) ? g_ctxT[(k - HID)*BB + b]
                              : g_h1T[p][(k - HID - VAL)*BB + b];
                    }
                    #pragma unroll
                    for (int i = 0; i < 2; i++) {
                        int li = i*256 + tid;
                        int k = (li >> 7)*224 + (it+1)*8 + ((li >> 4) & 7);
                        rb[i] = Wp[k*16 + (li & 15)];
                    }
                }
                #pragma unroll
                for (int kk = 0; kk < 8; kk++) {
                    float4 a  = *(float4*)&As[q*512 + kk*64 + r4];
                    float4 bq = *(float4*)&Bs[q*128 + kk*16 + c4];
                    float av[4] = {a.x, a.y, a.z, a.w};
                    float bv[4] = {bq.x, bq.y, bq.z, bq.w};
                    #pragma unroll
                    for (int i = 0; i < 4; i++)
                        #pragma unroll
                        for (int j = 0; j < 4; j++)
                            acc[i][j] += av[i] * bv[j];
                }
                __syncthreads();
            }
            float* red = sm;  // [4][1024]
            #pragma unroll
            for (int i = 0; i < 4; i++)
                *(float4*)&red[q*1024 + (r4+i)*16 + c4] =
                    make_float4(acc[i][0], acc[i][1], acc[i][2], acc[i][3]);
            __syncthreads();
            {   // fused LSTM1 cell epilogue: 64 rows x 4 j
                int r = tid & 63, jj = tid >> 6;
                float gsum[4];
                #pragma unroll
                for (int g = 0; g < 4; g++) {
                    float s = 0.f;
                    #pragma unroll
                    for (int qq = 0; qq < 4; qq++)
                        s += red[qq*1024 + r*16 + jj + 4*g];
                    gsum[g] = s;
                }
                int b = b0 + r, j = j0 + jj;
                float gi = gsum[0] + bih1[j]         + bhh1[j];
                float gf = gsum[1] + bih1[j +   H1S] + bhh1[j +   H1S];
                float gg = gsum[2] + bih1[j + 2*H1S] + bhh1[j + 2*H1S];
                float go = gsum[3] + bih1[j + 3*H1S] + bhh1[j + 3*H1S];
                int idx = j*BB + b;
                float c = sigf(gf) * g_c1T[idx] + sigf(gi) * tanhf(gg);
                g_c1T[idx] = c;
                g_h1T[pn][idx] = sigf(go) * tanhf(c);
            }
        }
        nb++; gbar(bid, nb);

        // ---------- Stage B: gemm2 + cell2 (register-prefetch pipelined) ----
        if (bid < 128) {
            const int b0 = (bid >> 5) * 32;
            const int n  = bid & 31;
            const int j0 = n * 4;
            const int q  = tid >> 6;          // 160 k per quadrant
            const int qt = tid & 63;
            const int r2 = (qt & 15) * 2;
            const int c4 = (qt >> 4) * 4;
            const float* Wp = g_W2p + (size_t)n * (640*16);
            float acc[2][4];
            #pragma unroll
            for (int i = 0; i < 2; i++)
                #pragma unroll
                for (int j = 0; j < 4; j++) acc[i][j] = 0.f;

            float* As = sm;           // [4][8][32]
            float* Bs = sm + 1024;    // [4][8][16]
            float ra[4], rb[2];

            #pragma unroll
            for (int i = 0; i < 4; i++) {
                int li = i*256 + tid;
                int k = (li >> 8)*160 + ((li >> 5) & 7);
                int b = b0 + (li & 31);
                ra[i] = (k < H1S) ? g_h1T[pn][k*BB + b]
                                  : g_h2T[p][(k - H1S)*BB + b];
            }
            #pragma unroll
            for (int i = 0; i < 2; i++) {
                int li = i*256 + tid;
                int k = (li >> 7)*160 + ((li >> 4) & 7);
                rb[i] = Wp[k*16 + (li & 15)];
            }

            for (int it = 0; it < 20; it++) {
                #pragma unroll
                for (int i = 0; i < 4; i++) {
                    int li = i*256 + tid;
                    As[(li >> 8)*256 + ((li >> 5) & 7)*32 + (li & 31)] = ra[i];
                }
                #pragma unroll
                for (int i = 0; i < 2; i++) {
                    int li = i*256 + tid;
                    Bs[(li >> 7)*128 + ((li >> 4) & 7)*16 + (li & 15)] = rb[i];
                }
                __syncthreads();
                if (it < 19) {
                    #pragma unroll
                    for (int i = 0; i < 4; i++) {
                        int li = i*256 + tid;
                        int k = (li >> 8)*160 + (it+1)*8 + ((li >> 5) & 7);
                        int b = b0 + (li & 31);
                        ra[i] = (k < H1S) ? g_h1T[pn][k*BB + b]
                                          : g_h2T[p][(k - H1S)*BB + b];
                    }
                    #pragma unroll
                    for (int i = 0; i < 2; i++) {
                        int li = i*256 + tid;
                        int k = (li >> 7)*160 + (it+1)*8 + ((li >> 4) & 7);
                        rb[i] = Wp[k*16 + (li & 15)];
                    }
                }
                #pragma unroll
                for (int kk = 0; kk < 8; kk++) {
                    float2 a  = *(float2*)&As[q*256 + kk*32 + r2];
                    float4 bq = *(float4*)&Bs[q*128 + kk*16 + c4];
                    float av[2] = {a.x, a.y};
                    float bv[4] = {bq.x, bq.y, bq.z, bq.w};
                    #pragma unroll
                    for (int i = 0; i < 2; i++)
                        #pragma unroll
                        for (int j = 0; j < 4; j++)
                            acc[i][j] += av[i] * bv[j];
                }
                __syncthreads();
            }
            float* red = sm;  // [4][512]
            #pragma unroll
            for (int i = 0; i < 2; i++)
                *(float4*)&red[q*512 + (r2+i)*16 + c4] =
                    make_float4(acc[i][0], acc[i][1], acc[i][2], acc[i][3]);
            __syncthreads();
            if (tid < 128) {   // 32 rows x 4 j
                int r = tid & 31, jj = tid >> 5;
                float gsum[4];
                #pragma unroll
                for (int g = 0; g < 4; g++) {
                    float s = 0.f;
                    #pragma unroll
                    for (int qq = 0; qq < 4; qq++)
                        s += red[qq*512 + r*16 + jj + 4*g];
                    gsum[g] = s;
                }
                int b = b0 + r, j = j0 + jj;
                float gi = gsum[0] + bih2[j]         + bhh2[j];
                float gf = gsum[1] + bih2[j +   KEY] + bhh2[j +   KEY];
                float gg = gsum[2] + bih2[j + 2*KEY] + bhh2[j + 2*KEY];
                float go = gsum[3] + bih2[j + 3*KEY] + bhh2[j + 3*KEY];
                int idx = j*BB + b;
                float c = sigf(gf) * g_c2T[idx] + sigf(gi) * tanhf(gg);
                g_c2T[idx] = c;
                float h = sigf(go) * tanhf(c);
                g_h2T[pn][idx] = h;
                g_h2ctxT[(size_t)j*NROWS + t*BB + b] = h;
            }
        }
        nb++; gbar(bid, nb);

        // ---------- Stage C: attention, two-pass smem softmax, no shuffles --
        if (bid < BB) {
            const int b = bid;
            const int lane = tid & 31, w = tid >> 5;   // 8 warps
            const int len = lens[b];
            float* s_p  = sm;           // [2048] energies -> probabilities
            float* s_pt = sm + 2048;    // [8][128] ctx partials
            float* s_h2 = sm + 3072;    // [128]
            float* s_r  = sm + 3200;    // [16] reduce scratch
            if (tid < 128) s_h2[tid] = g_h2T[pn][tid*BB + b];
            __syncthreads();

            // --- E pass: thread owns t0..t0+7 (contiguous) ---
            const int t0 = tid * 8;
            float ef[8];
            #pragma unroll
            for (int i = 0; i < 8; i++) ef[i] = 0.f;
            if (t0 < len) {
                const __half* kp = g_khT + (size_t)b*KEY*T_ENC + t0;
                #pragma unroll 4
                for (int k = 0; k < KEY; k++) {
                    uint4 u = *(const uint4*)(kp + (size_t)k*T_ENC);
                    float h = s_h2[k];
                    float2 f0 = __half22float2(((__half2*)&u)[0]);
                    float2 f1 = __half22float2(((__half2*)&u)[1]);
                    float2 f2 = __half22float2(((__half2*)&u)[2]);
                    float2 f3 = __half22float2(((__half2*)&u)[3]);
                    ef[0] += h*f0.x; ef[1] += h*f0.y;
                    ef[2] += h*f1.x; ef[3] += h*f1.y;
                    ef[4] += h*f2.x; ef[5] += h*f2.y;
                    ef[6] += h*f3.x; ef[7] += h*f3.y;
                }
            }
            float e[8];
            #pragma unroll
            for (int i = 0; i < 8; i++)
                e[i] = (t0 + i < len) ? ef[i] : -3.0e38f;

            // --- block max ---
            float tm = e[0];
            #pragma unroll
            for (int i = 1; i < 8; i++) tm = fmaxf(tm, e[i]);
            #pragma unroll
            for (int off = 16; off; off >>= 1)
                tm = fmaxf(tm, __shfl_xor_sync(~0u, tm, off));
            if (lane == 0) s_r[w] = tm;
            __syncthreads();
            float M = s_r[0];
            #pragma unroll
            for (int ww = 1; ww < 8; ww++) M = fmaxf(M, s_r[ww]);

            // --- p = exp(e-M), sum l ---
            float pv[8];
            float lsum = 0.f;
            #pragma unroll
            for (int i = 0; i < 8; i++) {
                pv[i] = expf(e[i] - M);
                lsum += pv[i];
            }
            *(float4*)&s_p[t0]     = make_float4(pv[0], pv[1], pv[2], pv[3]);
            *(float4*)&s_p[t0 + 4] = make_float4(pv[4], pv[5], pv[6], pv[7]);
            #pragma unroll
            for (int off = 16; off; off >>= 1)
                lsum += __shfl_xor_sync(~0u, lsum, off);
            if (lane == 0) s_r[8 + w] = lsum;
            __syncthreads();           // also publishes s_p
            float L = 0.f;
            #pragma unroll
            for (int ww = 0; ww < 8; ww++) L += s_r[8 + ww];
            const float Linv = 1.f / L;

            // --- V pass: ctx[v] = sum_t p[t]*V[t][b][v] ---
            const int vq = (tid & 31) * 4;   // v base (4 per thread)
            const int tg = tid >> 5;         // 0..7 (t mod 8), uniform per warp
            float a0 = 0.f, a1 = 0.f, a2 = 0.f, a3 = 0.f;
            const int itmax = (len + 7) >> 3;
            for (int it = 0; it < itmax; it++) {
                int tt = it*8 + tg;
                float pw = s_p[tt];          // broadcast within warp
                uint2 u = *(const uint2*)(g_vh + ((size_t)tt*BB + b)*VAL + vq);
                float2 f01 = __half22float2(((__half2*)&u)[0]);
                float2 f23 = __half22float2(((__half2*)&u)[1]);
                a0 += pw*f01.x; a1 += pw*f01.y;
                a2 += pw*f23.x; a3 += pw*f23.y;
            }
            *(float4*)&s_pt[tg*128 + vq] = make_float4(a0, a1, a2, a3);
            __syncthreads();
            if (tid < 128) {
                float s = 0.f;
                #pragma unroll
                for (int g8 = 0; g8 < 8; g8++) s += s_pt[g8*128 + tid];
                float cx = s * Linv;
                g_ctxT[tid*BB + b] = cx;
                g_h2ctxT[(size_t)(KEY + tid)*NROWS + t*BB + b] = cx;
            }
        }
        nb++; gbar(bid, nb);
    }
}

// ---------------- final logits GEMM -------------
__global__ __launch_bounds__(256) void pred_kernel(
    const float* __restrict__ Wlin, const float* __restrict__ blin,
    float* __restrict__ out)
{
    __shared__ float As[16][68];
    __shared__ float Bs[16][68];
    const int r0 = blockIdx.x * 64;
    const int v0 = blockIdx.y * 64;
    const int tid = threadIdx.x;
    const int m0 = (tid & 15) * 4;
    const int n0 = (tid >> 4) * 4;
    float acc[4][4] = {};

    for (int k0 = 0; k0 < 256; k0 += 16) {
        #pragma unroll
        for (int i = 0; i < 4; i++) {
            int li = i*256 + tid;
            int kk = li >> 6, m = li & 63;
            As[kk][m] = g_h2ctxT[(size_t)(k0 + kk)*NROWS + r0 + m];
        }
        #pragma unroll
        for (int i = 0; i < 4; i++) {
            int li = i*256 + tid;
            int n = li >> 4, kk = li & 15;
            int v = v0 + n;
            Bs[kk][n] = (v < VOCAB) ? Wlin[v*256 + k0 + kk] : 0.f;
        }
        __syncthreads();
        #pragma unroll
        for (int kk = 0; kk < 16; kk++) {
            float4 a = *(const float4*)&As[kk][m0];
            float4 bq = *(const float4*)&Bs[kk][n0];
            float av[4] = {a.x, a.y, a.z, a.w};
            float bv[4] = {bq.x, bq.y, bq.z, bq.w};
            #pragma unroll
            for (int i = 0; i < 4; i++)
                #pragma unroll
                for (int j = 0; j < 4; j++)
                    acc[i][j] += av[i] * bv[j];
        }
        __syncthreads();
    }
    #pragma unroll
    for (int i = 0; i < 4; i++) {
        int r = r0 + m0 + i;
        int b = r & 127, t = r >> 7;
        #pragma unroll
        for (int j = 0; j < 4; j++) {
            int v = v0 + n0 + j;
            if (v < VOCAB)
                out[((size_t)b*T_DEC + t)*VOCAB + v] = acc[i][j] + blin[v];
        }
    }
}

// ---------------- launch ----------------
extern "C" void kernel_launch(void* const* d_in, const int* in_sizes, int n_in,
                              void* d_out, int out_size)
{
    const float* keys      = (const float*)d_in[0];
    const float* values    = (const float*)d_in[1];
    const int*   lens      = (const int*)  d_in[2];
    const int*   text      = (const int*)  d_in[3];
    const float* emb_table = (const float*)d_in[4];
    const float* Wih1      = (const float*)d_in[5];
    const float* Whh1      = (const float*)d_in[6];
    const float* bih1      = (const float*)d_in[7];
    const float* bhh1      = (const float*)d_in[8];
    const float* Wih2      = (const float*)d_in[9];
    const float* Whh2      = (const float*)d_in[10];
    const float* bih2      = (const float*)d_in[11];
    const float* bhh2      = (const float*)d_in[12];
    const float* Wlin      = (const float*)d_in[13];
    const float* blin      = (const float*)d_in[14];
    float* out = (float*)d_out;

    reset_bar_kernel<<<1, 512>>>();
    decoder_kernel<<<NBLK, NTHR>>>(keys, values, lens, text, emb_table,
                                   Wih1, Whh1, bih1, bhh1,
                                   Wih2, Whh2, bih2, bhh2);
    pred_kernel<<<dim3(NROWS/64, (VOCAB + 63)/64), 256>>>(Wlin, blin, out);
}

// round 10
// speedup vs baseline: 4.3912x; 1.2837x over previous
#include <cuda_runtime.h>
#include <cuda_fp16.h>
#include <math.h>

#define BB 128       // batch
#define T_ENC 2048
#define T_DEC 256
#define HID 256
#define KEY 128
#define VAL 128
#define H1S 512      // lstm1 hidden
#define VOCAB 1000
#define NBLK 296     // 2 CTAs/SM * 148 SMs, all resident
#define NTHR 256
#define NROWS (T_DEC*BB)   // 32768

// ---------------- device scratch (static) ----------------
__device__ unsigned g_leaf[8*64];    // gbar-all leaves (256B apart)
__device__ unsigned g_root;
__device__ unsigned g_leafB[4*64];   // barB leaves (blocks 0-127)
__device__ unsigned g_rootB;
__device__ float g_embT[(size_t)T_DEC*HID*BB];          // [t][h][b]
__device__ float g_h2ctxT[(size_t)(KEY+VAL)*NROWS];     // [f][t*BB+b]
__device__ float g_h1T[H1S*BB];                         // [j][b] (single buf)
__device__ float g_c1T[H1S*BB];
__device__ float g_h2T[2][KEY*BB];
__device__ float g_c2T[KEY*BB];
__device__ float g_ctxT[VAL*BB];                        // [v][b]
__device__ float g_g1p[(size_t)2*128*16*64];            // partials [b0][n][ci][r]
__device__ float g_W1p[(size_t)128*896*16];             // [tile][k][16]
__device__ float g_W2p[(size_t)32*640*16];
__device__ __align__(16) __half g_khT[(size_t)BB*KEY*T_ENC];  // [b][k][t]
__device__ __align__(16) __half g_vh[(size_t)T_ENC*BB*VAL];   // [t][b][v]

// ---------------- barriers (monotonic, hierarchical) ----------------
__device__ __forceinline__ void gbar(int bid, unsigned ph) {
    __syncthreads();
    if (threadIdx.x == 0) {
        __threadfence();
        int g = bid & 7;                       // 37 blocks per leaf
        unsigned old = atomicAdd(&g_leaf[g*64], 1u);
        if (old == ph*37u - 1u) atomicAdd(&g_root, 1u);
        while (*(volatile unsigned*)&g_root < ph*8u) __nanosleep(32);
        __threadfence();
    }
    __syncthreads();
}
// barrier among blocks 0..127 only
__device__ __forceinline__ void barB(int bid, unsigned ph) {
    __syncthreads();
    if (threadIdx.x == 0) {
        __threadfence();
        int g = bid & 3;                       // 32 blocks per leaf
        unsigned old = atomicAdd(&g_leafB[g*64], 1u);
        if (old == ph*32u - 1u) atomicAdd(&g_rootB, 1u);
        while (*(volatile unsigned*)&g_rootB < ph*4u) __nanosleep(32);
        __threadfence();
    }
    __syncthreads();
}

__global__ void reset_bar_kernel() {
    int i = threadIdx.x;
    if (i < 8*64) g_leaf[i] = 0u;
    if (i < 4*64) g_leafB[i] = 0u;
    if (i == 0) { g_root = 0u; g_rootB = 0u; }
}

__device__ __forceinline__ float sigf(float x) { return 1.f / (1.f + expf(-x)); }

// ---------------- A': emb+h1 partial GEMM for step tnext -----------------
// job j in [0,256): b0sel=j>>7, n=j&127. Output: g_g1p[b0sel][n][16 ci][64 r]
__device__ __forceinline__ void aprime_job(int j, int tnext, float* sm, int tid) {
    const int b0 = (j >> 7) * 64;
    const int n  = j & 127;
    const int q  = tid >> 6;            // k-quadrant (192 k_local each)
    const int qt = tid & 63;
    const int r4 = (qt & 15) * 4;
    const int c4 = (qt >> 4) * 4;
    const float* Wp = g_W1p + (size_t)n * (896*16);
    float acc[4][4];
    #pragma unroll
    for (int i = 0; i < 4; i++)
        #pragma unroll
        for (int jj = 0; jj < 4; jj++) acc[i][jj] = 0.f;

    float* As = sm;           // [4][8][64]
    float* Bs = sm + 2048;    // [4][8][16]
    float ra[8], rb[2];

    // prefetch iter 0
    #pragma unroll
    for (int i = 0; i < 8; i++) {
        int li = i*256 + tid;
        int kl = (li >> 9)*192 + ((li >> 6) & 7);
        int b = b0 + (li & 63);
        ra[i] = (kl < HID) ? g_embT[((size_t)tnext*HID + kl)*BB + b]
                           : g_h1T[(kl - HID)*BB + b];
    }
    #pragma unroll
    for (int i = 0; i < 2; i++) {
        int li = i*256 + tid;
        int kl = (li >> 7)*192 + ((li >> 4) & 7);
        int kg = (kl < HID) ? kl : kl + VAL;
        rb[i] = Wp[kg*16 + (li & 15)];
    }

    for (int it = 0; it < 24; it++) {
        #pragma unroll
        for (int i = 0; i < 8; i++) {
            int li = i*256 + tid;
            As[(li >> 9)*512 + ((li >> 6) & 7)*64 + (li & 63)] = ra[i];
        }
        #pragma unroll
        for (int i = 0; i < 2; i++) {
            int li = i*256 + tid;
            Bs[(li >> 7)*128 + ((li >> 4) & 7)*16 + (li & 15)] = rb[i];
        }
        __syncthreads();
        if (it < 23) {
            #pragma unroll
            for (int i = 0; i < 8; i++) {
                int li = i*256 + tid;
                int kl = (li >> 9)*192 + (it+1)*8 + ((li >> 6) & 7);
                int b = b0 + (li & 63);
                ra[i] = (kl < HID) ? g_embT[((size_t)tnext*HID + kl)*BB + b]
                                   : g_h1T[(kl - HID)*BB + b];
            }
            #pragma unroll
            for (int i = 0; i < 2; i++) {
                int li = i*256 + tid;
                int kl = (li >> 7)*192 + (it+1)*8 + ((li >> 4) & 7);
                int kg = (kl < HID) ? kl : kl + VAL;
                rb[i] = Wp[kg*16 + (li & 15)];
            }
        }
        #pragma unroll
        for (int kk = 0; kk < 8; kk++) {
            float4 a  = *(float4*)&As[q*512 + kk*64 + r4];
            float4 bq = *(float4*)&Bs[q*128 + kk*16 + c4];
            float av[4] = {a.x, a.y, a.z, a.w};
            float bv[4] = {bq.x, bq.y, bq.z, bq.w};
            #pragma unroll
            for (int i = 0; i < 4; i++)
                #pragma unroll
                for (int jj = 0; jj < 4; jj++)
                    acc[i][jj] += av[i] * bv[jj];
        }
        __syncthreads();
    }
    float* red = sm;  // [4][1024]
    #pragma unroll
    for (int i = 0; i < 4; i++)
        *(float4*)&red[q*1024 + (r4+i)*16 + c4] =
            make_float4(acc[i][0], acc[i][1], acc[i][2], acc[i][3]);
    __syncthreads();
    {   // write partial: thread (r, cb) -> ci = cb*4..cb*4+3, coalesced over r
        int r = tid & 63, cb = tid >> 6;
        float* dst = g_g1p + ((size_t)(j >> 7)*128 + n)*16*64;
        #pragma unroll
        for (int i = 0; i < 4; i++) {
            int ci = cb*4 + i;
            float s = 0.f;
            #pragma unroll
            for (int qq = 0; qq < 4; qq++)
                s += red[qq*1024 + r*16 + ci];
            dst[ci*64 + r] = s;
        }
    }
    __syncthreads();   // protect red (==As) before any next job
}

// =============================================================================
// Persistent decoder kernel
// =============================================================================
__global__ __launch_bounds__(NTHR, 2) void decoder_kernel(
    const float* __restrict__ keys, const float* __restrict__ values,
    const int* __restrict__ lens, const int* __restrict__ text,
    const float* __restrict__ emb_table,
    const float* __restrict__ Wih1, const float* __restrict__ Whh1,
    const float* __restrict__ bih1, const float* __restrict__ bhh1,
    const float* __restrict__ Wih2, const float* __restrict__ Whh2,
    const float* __restrict__ bih2, const float* __restrict__ bhh2)
{
    __shared__ float sm[4160];
    const int tid = threadIdx.x;
    const int bid = blockIdx.x;
    const int gid = bid * NTHR + tid;
    const int gstride = NBLK * NTHR;   // 75776
    unsigned nb = 0, nbB = 0;

    // ---------------- pre-stage ----------------
    for (int i = gid; i < H1S*BB;   i += gstride) { g_h1T[i] = 0.f; g_c1T[i] = 0.f; }
    for (int i = gid; i < 2*KEY*BB; i += gstride) ((float*)g_h2T)[i] = 0.f;
    for (int i = gid; i < KEY*BB;   i += gstride) g_c2T[i] = 0.f;
    for (int i = gid; i < VAL*BB;   i += gstride) g_ctxT[i] = 0.f;

    // embedding gather -> [t][h][b]
    for (int i = gid; i < T_DEC*HID*BB; i += gstride) {
        int b = i & (BB-1);
        int f = i >> 7;
        int h = f & (HID-1);
        int t = f >> 8;
        g_embT[i] = emb_table[text[b*T_DEC + t]*HID + h];
    }

    // pack W1 -> [128 tiles][896 k][16 cols] (gate-grouped: ci = gate*4 + jj)
    for (int i = gid; i < 128*896*16; i += gstride) {
        int ci = i & 15;
        int k  = (i >> 4) % 896;
        int n  = i / (896*16);
        int c  = n*4 + (ci & 3) + H1S * (ci >> 2);
        g_W1p[i] = (k < HID+VAL) ? Wih1[c*(HID+VAL) + k]
                                 : Whh1[c*H1S + (k - HID - VAL)];
    }
    // pack W2 -> [32 tiles][640 k][16 cols]
    for (int i = gid; i < 32*640*16; i += gstride) {
        int ci = i & 15;
        int k  = (i >> 4) % 640;
        int n  = i / (640*16);
        int c  = n*4 + (ci & 3) + KEY * (ci >> 2);
        g_W2p[i] = (k < H1S) ? Wih2[c*H1S + k] : Whh2[c*KEY + (k - H1S)];
    }

    // convert V to fp16 ([t][b][v] layout kept)
    {
        const int n4 = (T_ENC*BB*VAL) / 4;
        const float4* v4 = (const float4*)values;
        __half2* vh2 = (__half2*)g_vh;
        for (int i = gid; i < n4; i += gstride) {
            float4 f = v4[i];
            vh2[2*i]   = __floats2half2_rn(f.x, f.y);
            vh2[2*i+1] = __floats2half2_rn(f.z, f.w);
        }
    }

    // transpose K -> fp16 [b][k][t] via smem tiles (64 t x 32 k per job)
    for (int j = bid; j < 128*4*32; j += NBLK) {
        int b  = j >> 7;
        int kt = (j >> 5) & 3;
        int tt = j & 31;
        float* st = sm;           // [64][33]
        #pragma unroll
        for (int p8 = 0; p8 < 8; p8++) {
            int trow = p8*8 + (tid >> 5);
            int kcol = tid & 31;
            st[trow*33 + kcol] =
                keys[((size_t)(tt*64 + trow)*BB + b)*KEY + kt*32 + kcol];
        }
        __syncthreads();
        #pragma unroll
        for (int p4 = 0; p4 < 8; p4++) {
            int kr   = p4*4 + (tid >> 6);
            int tcol = tid & 63;
            g_khT[((size_t)b*KEY + kt*32 + kr)*T_ENC + tt*64 + tcol] =
                __float2half_rn(st[tcol*33 + kr]);
        }
        __syncthreads();
    }
    nb++; gbar(bid, nb);

    // ---------------- A'_0: partial gates for t=0 (h1 = 0, emb_0) ----------
    if (bid < 256) aprime_job(bid, 0, sm, tid);
    nb++; gbar(bid, nb);

    // ================= decode loop =================
    for (int t = 0; t < T_DEC; t++) {
        const int p = t & 1, pn = p ^ 1;

        // ---------- Interval 1: A'' = ctx-part GEMM (K=128) + cell1 ----------
        if (bid < 256) {
            const int b0 = (bid >> 7) * 64;
            const int n  = bid & 127;
            const int j0 = n * 4;
            const int q  = tid >> 6;          // 32 k per quadrant
            const int qt = tid & 63;
            const int r4 = (qt & 15) * 4;
            const int c4 = (qt >> 4) * 4;
            const float* Wp = g_W1p + (size_t)n * (896*16);
            float acc[4][4];
            #pragma unroll
            for (int i = 0; i < 4; i++)
                #pragma unroll
                for (int jj = 0; jj < 4; jj++) acc[i][jj] = 0.f;

            float* As = sm;           // [4][8][64]
            float* Bs = sm + 2048;    // [4][8][16]

            for (int it = 0; it < 4; it++) {
                #pragma unroll
                for (int i = 0; i < 8; i++) {
                    int li = i*256 + tid;
                    int k = (li >> 9)*32 + it*8 + ((li >> 6) & 7);
                    As[(li >> 9)*512 + ((li >> 6) & 7)*64 + (li & 63)] =
                        g_ctxT[k*BB + b0 + (li & 63)];
                }
                #pragma unroll
                for (int i = 0; i < 2; i++) {
                    int li = i*256 + tid;
                    int k = (li >> 7)*32 + it*8 + ((li >> 4) & 7);
                    Bs[(li >> 7)*128 + ((li >> 4) & 7)*16 + (li & 15)] =
                        Wp[(HID + k)*16 + (li & 15)];
                }
                __syncthreads();
                #pragma unroll
                for (int kk = 0; kk < 8; kk++) {
                    float4 a  = *(float4*)&As[q*512 + kk*64 + r4];
                    float4 bq = *(float4*)&Bs[q*128 + kk*16 + c4];
                    float av[4] = {a.x, a.y, a.z, a.w};
                    float bv[4] = {bq.x, bq.y, bq.z, bq.w};
                    #pragma unroll
                    for (int i = 0; i < 4; i++)
                        #pragma unroll
                        for (int jj = 0; jj < 4; jj++)
                            acc[i][jj] += av[i] * bv[jj];
                }
                __syncthreads();
            }
            float* red = sm;  // [4][1024]
            #pragma unroll
            for (int i = 0; i < 4; i++)
                *(float4*)&red[q*1024 + (r4+i)*16 + c4] =
                    make_float4(acc[i][0], acc[i][1], acc[i][2], acc[i][3]);
            __syncthreads();
            {   // epilogue: partial + ctx-part + bias -> cell1
                int r = tid & 63, jj = tid >> 6;
                const float* par = g_g1p + ((size_t)(bid >> 7)*128 + n)*16*64;
                float gsum[4];
                #pragma unroll
                for (int g = 0; g < 4; g++) {
                    int ci = jj + 4*g;
                    float s = par[ci*64 + r];
                    #pragma unroll
                    for (int qq = 0; qq < 4; qq++)
                        s += red[qq*1024 + r*16 + ci];
                    gsum[g] = s;
                }
                int b = b0 + r, j = j0 + jj;
                float gi = gsum[0] + bih1[j]         + bhh1[j];
                float gf = gsum[1] + bih1[j +   H1S] + bhh1[j +   H1S];
                float gg = gsum[2] + bih1[j + 2*H1S] + bhh1[j + 2*H1S];
                float go = gsum[3] + bih1[j + 3*H1S] + bhh1[j + 3*H1S];
                int idx = j*BB + b;
                float c = sigf(gf) * g_c1T[idx] + sigf(gi) * tanhf(gg);
                g_c1T[idx] = c;
                g_h1T[idx] = sigf(go) * tanhf(c);
            }
        }
        nb++; gbar(bid, nb);

        // ---------- Interval 2+3: {B -> barB -> C} on 0-127  ||  A'_{t+1} ----
        if (bid < 128) {
            // ----- Stage B: gemm2 + cell2 -----
            const int b0 = (bid >> 5) * 32;
            const int n  = bid & 31;
            const int j0 = n * 4;
            const int q  = tid >> 6;          // 160 k per quadrant
            const int qt = tid & 63;
            const int r2 = (qt & 15) * 2;
            const int c4 = (qt >> 4) * 4;
            const float* Wp = g_W2p + (size_t)n * (640*16);
            float acc[2][4];
            #pragma unroll
            for (int i = 0; i < 2; i++)
                #pragma unroll
                for (int jj = 0; jj < 4; jj++) acc[i][jj] = 0.f;

            float* As = sm;           // [4][8][32]
            float* Bs = sm + 1024;    // [4][8][16]
            float ra[4], rb[2];

            #pragma unroll
            for (int i = 0; i < 4; i++) {
                int li = i*256 + tid;
                int k = (li >> 8)*160 + ((li >> 5) & 7);
                int b = b0 + (li & 31);
                ra[i] = (k < H1S) ? g_h1T[k*BB + b]
                                  : g_h2T[p][(k - H1S)*BB + b];
            }
            #pragma unroll
            for (int i = 0; i < 2; i++) {
                int li = i*256 + tid;
                int k = (li >> 7)*160 + ((li >> 4) & 7);
                rb[i] = Wp[k*16 + (li & 15)];
            }

            for (int it = 0; it < 20; it++) {
                #pragma unroll
                for (int i = 0; i < 4; i++) {
                    int li = i*256 + tid;
                    As[(li >> 8)*256 + ((li >> 5) & 7)*32 + (li & 31)] = ra[i];
                }
                #pragma unroll
                for (int i = 0; i < 2; i++) {
                    int li = i*256 + tid;
                    Bs[(li >> 7)*128 + ((li >> 4) & 7)*16 + (li & 15)] = rb[i];
                }
                __syncthreads();
                if (it < 19) {
                    #pragma unroll
                    for (int i = 0; i < 4; i++) {
                        int li = i*256 + tid;
                        int k = (li >> 8)*160 + (it+1)*8 + ((li >> 5) & 7);
                        int b = b0 + (li & 31);
                        ra[i] = (k < H1S) ? g_h1T[k*BB + b]
                                          : g_h2T[p][(k - H1S)*BB + b];
                    }
                    #pragma unroll
                    for (int i = 0; i < 2; i++) {
                        int li = i*256 + tid;
                        int k = (li >> 7)*160 + (it+1)*8 + ((li >> 4) & 7);
                        rb[i] = Wp[k*16 + (li & 15)];
                    }
                }
                #pragma unroll
                for (int kk = 0; kk < 8; kk++) {
                    float2 a  = *(float2*)&As[q*256 + kk*32 + r2];
                    float4 bq = *(float4*)&Bs[q*128 + kk*16 + c4];
                    float av[2] = {a.x, a.y};
                    float bv[4] = {bq.x, bq.y, bq.z, bq.w};
                    #pragma unroll
                    for (int i = 0; i < 2; i++)
                        #pragma unroll
                        for (int jj = 0; jj < 4; jj++)
                            acc[i][jj] += av[i] * bv[jj];
                }
                __syncthreads();
            }
            float* red = sm;  // [4][512]
            #pragma unroll
            for (int i = 0; i < 2; i++)
                *(float4*)&red[q*512 + (r2+i)*16 + c4] =
                    make_float4(acc[i][0], acc[i][1], acc[i][2], acc[i][3]);
            __syncthreads();
            if (tid < 128) {   // 32 rows x 4 j
                int r = tid & 31, jj = tid >> 5;
                float gsum[4];
                #pragma unroll
                for (int g = 0; g < 4; g++) {
                    float s = 0.f;
                    #pragma unroll
                    for (int qq = 0; qq < 4; qq++)
                        s += red[qq*512 + r*16 + jj + 4*g];
                    gsum[g] = s;
                }
                int b = b0 + r, j = j0 + jj;
                float gi = gsum[0] + bih2[j]         + bhh2[j];
                float gf = gsum[1] + bih2[j +   KEY] + bhh2[j +   KEY];
                float gg = gsum[2] + bih2[j + 2*KEY] + bhh2[j + 2*KEY];
                float go = gsum[3] + bih2[j + 3*KEY] + bhh2[j + 3*KEY];
                int idx = j*BB + b;
                float c = sigf(gf) * g_c2T[idx] + sigf(gi) * tanhf(gg);
                g_c2T[idx] = c;
                float h = sigf(go) * tanhf(c);
                g_h2T[pn][idx] = h;
                g_h2ctxT[(size_t)j*NROWS + t*BB + b] = h;
            }
            nbB++; barB(bid, nbB);

            // ----- Stage C: attention, two-pass smem softmax -----
            {
                const int b = bid;
                const int lane = tid & 31, w = tid >> 5;
                const int len = lens[b];
                float* s_p  = sm;           // [2048]
                float* s_pt = sm + 2048;    // [8][128]
                float* s_h2 = sm + 3072;    // [128]
                float* s_r  = sm + 3200;    // [16]
                if (tid < 128) s_h2[tid] = g_h2T[pn][tid*BB + b];
                __syncthreads();

                const int t0 = tid * 8;
                float ef[8];
                #pragma unroll
                for (int i = 0; i < 8; i++) ef[i] = 0.f;
                if (t0 < len) {
                    const __half* kp = g_khT + (size_t)b*KEY*T_ENC + t0;
                    #pragma unroll 4
                    for (int k = 0; k < KEY; k++) {
                        uint4 u = *(const uint4*)(kp + (size_t)k*T_ENC);
                        float h = s_h2[k];
                        float2 f0 = __half22float2(((__half2*)&u)[0]);
                        float2 f1 = __half22float2(((__half2*)&u)[1]);
                        float2 f2 = __half22float2(((__half2*)&u)[2]);
                        float2 f3 = __half22float2(((__half2*)&u)[3]);
                        ef[0] += h*f0.x; ef[1] += h*f0.y;
                        ef[2] += h*f1.x; ef[3] += h*f1.y;
                        ef[4] += h*f2.x; ef[5] += h*f2.y;
                        ef[6] += h*f3.x; ef[7] += h*f3.y;
                    }
                }
                float e[8];
                #pragma unroll
                for (int i = 0; i < 8; i++)
                    e[i] = (t0 + i < len) ? ef[i] : -3.0e38f;

                float tm = e[0];
                #pragma unroll
                for (int i = 1; i < 8; i++) tm = fmaxf(tm, e[i]);
                #pragma unroll
                for (int off = 16; off; off >>= 1)
                    tm = fmaxf(tm, __shfl_xor_sync(~0u, tm, off));
                if (lane == 0) s_r[w] = tm;
                __syncthreads();
                float M = s_r[0];
                #pragma unroll
                for (int ww = 1; ww < 8; ww++) M = fmaxf(M, s_r[ww]);

                float pv[8];
                float lsum = 0.f;
                #pragma unroll
                for (int i = 0; i < 8; i++) {
                    pv[i] = expf(e[i] - M);
                    lsum += pv[i];
                }
                *(float4*)&s_p[t0]     = make_float4(pv[0], pv[1], pv[2], pv[3]);
                *(float4*)&s_p[t0 + 4] = make_float4(pv[4], pv[5], pv[6], pv[7]);
                #pragma unroll
                for (int off = 16; off; off >>= 1)
                    lsum += __shfl_xor_sync(~0u, lsum, off);
                if (lane == 0) s_r[8 + w] = lsum;
                __syncthreads();
                float L = 0.f;
                #pragma unroll
                for (int ww = 0; ww < 8; ww++) L += s_r[8 + ww];
                const float Linv = 1.f / L;

                const int vq = (tid & 31) * 4;
                const int tg = tid >> 5;
                float a0 = 0.f, a1 = 0.f, a2 = 0.f, a3 = 0.f;
                const int itmax = (len + 7) >> 3;
                for (int it = 0; it < itmax; it++) {
                    int tt = it*8 + tg;
                    float pw = s_p[tt];
                    uint2 u = *(const uint2*)(g_vh + ((size_t)tt*BB + b)*VAL + vq);
                    float2 f01 = __half22float2(((__half2*)&u)[0]);
                    float2 f23 = __half22float2(((__half2*)&u)[1]);
                    a0 += pw*f01.x; a1 += pw*f01.y;
                    a2 += pw*f23.x; a3 += pw*f23.y;
                }
                *(float4*)&s_pt[tg*128 + vq] = make_float4(a0, a1, a2, a3);
                __syncthreads();
                if (tid < 128) {
                    float s = 0.f;
                    #pragma unroll
                    for (int g8 = 0; g8 < 8; g8++) s += s_pt[g8*128 + tid];
                    float cx = s * Linv;
                    g_ctxT[tid*BB + b] = cx;
                    g_h2ctxT[(size_t)(KEY + tid)*NROWS + t*BB + b] = cx;
                }
            }
        } else if (t + 1 < T_DEC) {
            // ----- A'_{t+1} on blocks 128-295, pairing-aware job split -----
            int j0_, j1_ = -1;
            if (bid < 148)      { j0_ = 216 + (bid - 128); }           // paired A'+A'
            else if (bid < 236) { j0_ = bid - 148; j1_ = bid - 20; }   // 2 jobs
            else if (bid < 276) { j0_ = bid - 148; }
            else                { j0_ = 236 + (bid - 276); }           // paired A'+A'
            aprime_job(j0_, t + 1, sm, tid);
            if (j1_ >= 0) aprime_job(j1_, t + 1, sm, tid);
        }
        nb++; gbar(bid, nb);
    }
}

// ---------------- final logits GEMM -------------
__global__ __launch_bounds__(256) void pred_kernel(
    const float* __restrict__ Wlin, const float* __restrict__ blin,
    float* __restrict__ out)
{
    __shared__ float As[16][68];
    __shared__ float Bs[16][68];
    const int r0 = blockIdx.x * 64;
    const int v0 = blockIdx.y * 64;
    const int tid = threadIdx.x;
    const int m0 = (tid & 15) * 4;
    const int n0 = (tid >> 4) * 4;
    float acc[4][4] = {};

    for (int k0 = 0; k0 < 256; k0 += 16) {
        #pragma unroll
        for (int i = 0; i < 4; i++) {
            int li = i*256 + tid;
            int kk = li >> 6, m = li & 63;
            As[kk][m] = g_h2ctxT[(size_t)(k0 + kk)*NROWS + r0 + m];
        }
        #pragma unroll
        for (int i = 0; i < 4; i++) {
            int li = i*256 + tid;
            int n = li >> 4, kk = li & 15;
            int v = v0 + n;
            Bs[kk][n] = (v < VOCAB) ? Wlin[v*256 + k0 + kk] : 0.f;
        }
        __syncthreads();
        #pragma unroll
        for (int kk = 0; kk < 16; kk++) {
            float4 a = *(const float4*)&As[kk][m0];
            float4 bq = *(const float4*)&Bs[kk][n0];
            float av[4] = {a.x, a.y, a.z, a.w};
            float bv[4] = {bq.x, bq.y, bq.z, bq.w};
            #pragma unroll
            for (int i = 0; i < 4; i++)
                #pragma unroll
                for (int j = 0; j < 4; j++)
                    acc[i][j] += av[i] * bv[j];
        }
        __syncthreads();
    }
    #pragma unroll
    for (int i = 0; i < 4; i++) {
        int r = r0 + m0 + i;
        int b = r & 127, t = r >> 7;
        #pragma unroll
        for (int j = 0; j < 4; j++) {
            int v = v0 + n0 + j;
            if (v < VOCAB)
                out[((size_t)b*T_DEC + t)*VOCAB + v] = acc[i][j] + blin[v];
        }
    }
}

// ---------------- launch (decoder FIRST so ncu -s 5 lands on it) ---------
extern "C" void kernel_launch(void* const* d_in, const int* in_sizes, int n_in,
                              void* d_out, int out_size)
{
    const float* keys      = (const float*)d_in[0];
    const float* values    = (const float*)d_in[1];
    const int*   lens      = (const int*)  d_in[2];
    const int*   text      = (const int*)  d_in[3];
    const float* emb_table = (const float*)d_in[4];
    const float* Wih1      = (const float*)d_in[5];
    const float* Whh1      = (const float*)d_in[6];
    const float* bih1      = (const float*)d_in[7];
    const float* bhh1      = (const float*)d_in[8];
    const float* Wih2      = (const float*)d_in[9];
    const float* Whh2      = (const float*)d_in[10];
    const float* bih2      = (const float*)d_in[11];
    const float* bhh2      = (const float*)d_in[12];
    const float* Wlin      = (const float*)d_in[13];
    const float* blin      = (const float*)d_in[14];
    float* out = (float*)d_out;

    // Barrier counters are zero-initialized statically; reset_bar_kernel at the
    // END of each launch restores that invariant for the next replay.
    decoder_kernel<<<NBLK, NTHR>>>(keys, values, lens, text, emb_table,
                                   Wih1, Whh1, bih1, bhh1,
                                   Wih2, Whh2, bih2, bhh2);
    pred_kernel<<<dim3(NROWS/64, (VOCAB + 63)/64), 256>>>(Wlin, blin, out);
    reset_bar_kernel<<<1, 512>>>();
}